// round 3
// baseline (speedup 1.0000x reference)
#include <cuda_runtime.h>
#include <stdint.h>

// ---------------------------------------------------------------------------
// Transfer_35399120453953:
//   gathered    = features[atom_indices]            [E, 64]
//   transferred = segment_sum(gathered, domain_ids) [M, 64]   (domain_ids sorted)
//   out         = transferred @ W + b               [M, 128]
// ---------------------------------------------------------------------------

#define C_IN   64
#define C_OUT  128
#define WARPS_PER_BLOCK 8
#define DOMS_PER_WARP   4
#define DOMS_PER_BLOCK  (WARPS_PER_BLOCK * DOMS_PER_WARP)

__device__ int g_offsets[1048577];

// dtype sniff: int64 LE => high words of first 16 entries are 0.
// atom_indices is random in [0, N_ATOMS) so int32 data fails this test w.h.p.
__device__ __forceinline__ int detect_is64(const void* p_) {
    const int* p = (const int*)p_;
    int all_zero = 1;
    #pragma unroll
    for (int k = 0; k < 16; k++) all_zero &= (p[2 * k + 1] == 0);
    return all_zero;
}

// evict-first (streaming) index load
__device__ __forceinline__ long long load_index_cs(const void* p, int e, int is64) {
    if (is64) return __ldcs(((const long long*)p) + e);
    return (long long)__ldcs(((const int*)p) + e);
}

// ---------------------------------------------------------------------------
// Kernel 1: offsets[d] = lower_bound(domain_ids, d) for d in [0, M]
// ---------------------------------------------------------------------------
__global__ void compute_offsets_kernel(const void* __restrict__ domain_ids,
                                       const void* __restrict__ atom_indices,
                                       int E, int M) {
    const int is64 = detect_is64(atom_indices);
    int d = blockIdx.x * blockDim.x + threadIdx.x;
    if (d > M) return;
    int lo = 0, hi = E;
    while (lo < hi) {
        int mid = (lo + hi) >> 1;
        long long v = load_index_cs(domain_ids, mid, is64);
        if (v < (long long)d) lo = mid + 1; else hi = mid;
    }
    g_offsets[d] = lo;
}

// ---------------------------------------------------------------------------
// Kernel 2: fused gather + segment-sum + [64]x[64,128] projection.
// One warp handles 4 consecutive domains, INTERLEAVED in a joint loop:
// each iteration issues up to 4 independent (index, 512B-feature) load pairs
// under warp-uniform predicates -> ~4x memory-level parallelism vs serial.
// Lane layout: 16 lanes x float4 cover one 256B row; lane halves take
// even/odd entries (2 rows per load instruction), merged by shfl_xor(16).
// ---------------------------------------------------------------------------
__global__ __launch_bounds__(WARPS_PER_BLOCK * 32)
void transfer_fused_kernel(const float* __restrict__ features,
                           const void* __restrict__ atom_indices,
                           const float* __restrict__ W,
                           const float* __restrict__ b,
                           float* __restrict__ out,
                           int M) {
    __shared__ float Ws[C_IN * C_OUT];                           // 32 KB
    __shared__ float bs[C_OUT];
    __shared__ float sums[WARPS_PER_BLOCK][DOMS_PER_WARP][C_IN]; // 8 KB

    const int tid  = threadIdx.x;
    const int warp = tid >> 5;
    const int lane = tid & 31;

    #pragma unroll
    for (int i = tid; i < C_IN * C_OUT; i += WARPS_PER_BLOCK * 32)
        Ws[i] = W[i];
    if (tid < C_OUT) bs[tid] = b[tid];
    __syncthreads();

    const int is64  = detect_is64(atom_indices);
    const int dbase = (blockIdx.x * WARPS_PER_BLOCK + warp) * DOMS_PER_WARP;
    if (dbase >= M) return;

    const int half = lane >> 4;   // 0: even entries, 1: odd entries
    const int l16  = lane & 15;   // floats 4*l16 .. 4*l16+3 of the row

    // ---- phase 1: interleaved per-domain segment sums ----
    int cur[DOMS_PER_WARP], fin[DOMS_PER_WARP];
    float4 acc[DOMS_PER_WARP];
    #pragma unroll
    for (int g = 0; g < DOMS_PER_WARP; g++) {
        const int d = dbase + g;
        if (d < M) { cur[g] = g_offsets[d] + half; fin[g] = g_offsets[d + 1]; }
        else       { cur[g] = 0;                   fin[g] = 0; }
        acc[g] = make_float4(0.f, 0.f, 0.f, 0.f);
    }

    for (;;) {
        bool p[DOMS_PER_WARP];
        bool any = false;
        #pragma unroll
        for (int g = 0; g < DOMS_PER_WARP; g++) {
            p[g] = (cur[g] < fin[g]);
            any |= p[g];
        }
        if (!any) break;

        // batch the 4 independent index loads, then the 4 feature loads
        long long a[DOMS_PER_WARP];
        #pragma unroll
        for (int g = 0; g < DOMS_PER_WARP; g++)
            a[g] = p[g] ? load_index_cs(atom_indices, cur[g], is64) : 0;

        float4 v[DOMS_PER_WARP];
        #pragma unroll
        for (int g = 0; g < DOMS_PER_WARP; g++)
            if (p[g]) v[g] = __ldg(((const float4*)(features + a[g] * C_IN)) + l16);

        #pragma unroll
        for (int g = 0; g < DOMS_PER_WARP; g++) {
            if (p[g]) {
                acc[g].x += v[g].x; acc[g].y += v[g].y;
                acc[g].z += v[g].z; acc[g].w += v[g].w;
                cur[g] += 2;
            }
        }
    }

    #pragma unroll
    for (int g = 0; g < DOMS_PER_WARP; g++) {
        acc[g].x += __shfl_xor_sync(0xffffffffu, acc[g].x, 16);
        acc[g].y += __shfl_xor_sync(0xffffffffu, acc[g].y, 16);
        acc[g].z += __shfl_xor_sync(0xffffffffu, acc[g].z, 16);
        acc[g].w += __shfl_xor_sync(0xffffffffu, acc[g].w, 16);
        if (half == 0)
            ((float4*)&sums[warp][g][0])[l16] = acc[g];
    }
    __syncwarp();

    // ---- phase 2: out[d][j] = b[j] + sum_c sums[d][c] * W[c][j] ----
    const float4* Ws4 = (const float4*)Ws;
    const float4  bv  = ((const float4*)bs)[lane];

    float4 o[DOMS_PER_WARP];
    #pragma unroll
    for (int g = 0; g < DOMS_PER_WARP; g++) o[g] = bv;

    #pragma unroll 8
    for (int c = 0; c < C_IN; c++) {
        const float4 w = Ws4[c * (C_OUT / 4) + lane];
        #pragma unroll
        for (int g = 0; g < DOMS_PER_WARP; g++) {
            const float s = sums[warp][g][c];
            o[g].x = fmaf(s, w.x, o[g].x);
            o[g].y = fmaf(s, w.y, o[g].y);
            o[g].z = fmaf(s, w.z, o[g].z);
            o[g].w = fmaf(s, w.w, o[g].w);
        }
    }

    #pragma unroll
    for (int g = 0; g < DOMS_PER_WARP; g++) {
        const int d = dbase + g;
        if (d < M)
            __stcs(((float4*)(out + (long long)d * C_OUT)) + lane, o[g]);
    }
}

// ---------------------------------------------------------------------------
extern "C" void kernel_launch(void* const* d_in, const int* in_sizes, int n_in,
                              void* d_out, int out_size) {
    const float* features     = (const float*)d_in[0];
    const void*  atom_indices = d_in[1];
    const void*  domain_ids   = d_in[2];
    const float* W            = (const float*)d_in[4];
    const float* b            = (const float*)d_in[5];
    float*       out          = (float*)d_out;

    const int E = in_sizes[1];
    const int M = out_size / C_OUT;

    const int off_threads = 256;
    const int off_blocks  = (M + 1 + off_threads - 1) / off_threads;
    compute_offsets_kernel<<<off_blocks, off_threads>>>(domain_ids, atom_indices, E, M);

    const int blocks = (M + DOMS_PER_BLOCK - 1) / DOMS_PER_BLOCK;
    transfer_fused_kernel<<<blocks, WARPS_PER_BLOCK * 32>>>(
        features, atom_indices, W, b, out, M);
}

// round 4
// speedup vs baseline: 1.1577x; 1.1577x over previous
#include <cuda_runtime.h>
#include <stdint.h>

// ---------------------------------------------------------------------------
// Transfer_35399120453953:
//   gathered    = features[atom_indices]            [E, 64]
//   transferred = segment_sum(gathered, domain_ids) [M, 64]   (domain_ids sorted)
//   out         = transferred @ W + b               [M, 128]
// ---------------------------------------------------------------------------

#define C_IN   64
#define C_OUT  128
#define WARPS_PER_BLOCK 8
#define DOMS_PER_WARP   4
#define DOMS_PER_BLOCK  (WARPS_PER_BLOCK * DOMS_PER_WARP)

__device__ int g_offsets[1048577];

// dtype sniff: int64 LE => high words of first 16 entries are 0.
// atom_indices is random in [0, N_ATOMS) so int32 data fails this w.h.p.
__device__ __forceinline__ int detect_is64(const void* p_) {
    const int* p = (const int*)p_;
    int all_zero = 1;
    #pragma unroll
    for (int k = 0; k < 16; k++) all_zero &= (p[2 * k + 1] == 0);
    return all_zero;
}

// evict-first (streaming) index load: keep L2 for the feature table
__device__ __forceinline__ long long load_index_cs(const void* p, int e, int is64) {
    if (is64) return __ldcs(((const long long*)p) + e);
    return (long long)__ldcs(((const int*)p) + e);
}

// ---------------------------------------------------------------------------
// Kernel 1: offsets[d] = lower_bound(domain_ids, d) for d in [0, M]
// ---------------------------------------------------------------------------
__global__ void compute_offsets_kernel(const void* __restrict__ domain_ids,
                                       const void* __restrict__ atom_indices,
                                       int E, int M) {
    const int is64 = detect_is64(atom_indices);
    int d = blockIdx.x * blockDim.x + threadIdx.x;
    if (d > M) return;
    int lo = 0, hi = E;
    while (lo < hi) {
        int mid = (lo + hi) >> 1;
        long long v = load_index_cs(domain_ids, mid, is64);
        if (v < (long long)d) lo = mid + 1; else hi = mid;
    }
    g_offsets[d] = lo;
}

// ---------------------------------------------------------------------------
// Kernel 2: fused gather + segment-sum + [64]x[64,128] projection.
// One warp handles 4 consecutive domains (sequentially — the round-2
// structure that measured best).
//   phase 1: 16 lanes x float4 cover one 256B feature row; lane halves take
//            even/odd entries (2 rows / warp-load = 512B), unroll 8 for MLP,
//            merged with shfl_xor(16).
//   phase 2: sums staged in smem; lane j -> output columns 4j..4j+3 via
//            float4 W reads from smem, amortized over 4 batched domains.
// __launch_bounds__(256, 5): smem (41KB) allows 5 blocks/SM; clamp regs to
// ~51 so the RF does too -> 40 warps/SM for latency hiding.
// ---------------------------------------------------------------------------
__global__ __launch_bounds__(WARPS_PER_BLOCK * 32, 5)
void transfer_fused_kernel(const float* __restrict__ features,
                           const void* __restrict__ atom_indices,
                           const float* __restrict__ W,
                           const float* __restrict__ b,
                           float* __restrict__ out,
                           int M) {
    __shared__ float Ws[C_IN * C_OUT];                           // 32 KB
    __shared__ float bs[C_OUT];
    __shared__ float sums[WARPS_PER_BLOCK][DOMS_PER_WARP][C_IN]; // 8 KB

    const int tid  = threadIdx.x;
    const int warp = tid >> 5;
    const int lane = tid & 31;

    #pragma unroll
    for (int i = tid; i < C_IN * C_OUT; i += WARPS_PER_BLOCK * 32)
        Ws[i] = W[i];
    if (tid < C_OUT) bs[tid] = b[tid];
    __syncthreads();

    const int is64  = detect_is64(atom_indices);
    const int dbase = (blockIdx.x * WARPS_PER_BLOCK + warp) * DOMS_PER_WARP;
    if (dbase >= M) return;

    const int half = lane >> 4;   // 0: even entries, 1: odd entries
    const int l16  = lane & 15;   // floats 4*l16 .. 4*l16+3 of the row

    // ---- phase 1: per-domain segment sums ----
    #pragma unroll
    for (int g = 0; g < DOMS_PER_WARP; g++) {
        const int d = dbase + g;
        float4 acc = make_float4(0.f, 0.f, 0.f, 0.f);
        if (d < M) {
            const int s0 = g_offsets[d];
            const int s1 = g_offsets[d + 1];
            #pragma unroll 8
            for (int e = s0 + half; e < s1; e += 2) {
                const long long a = load_index_cs(atom_indices, e, is64);
                const float4 v =
                    __ldg(((const float4*)(features + a * C_IN)) + l16);
                acc.x += v.x; acc.y += v.y; acc.z += v.z; acc.w += v.w;
            }
        }
        // combine even/odd halves
        acc.x += __shfl_xor_sync(0xffffffffu, acc.x, 16);
        acc.y += __shfl_xor_sync(0xffffffffu, acc.y, 16);
        acc.z += __shfl_xor_sync(0xffffffffu, acc.z, 16);
        acc.w += __shfl_xor_sync(0xffffffffu, acc.w, 16);
        if (half == 0)
            ((float4*)&sums[warp][g][0])[l16] = acc;
    }
    __syncwarp();

    // ---- phase 2: out[d][j] = b[j] + sum_c sums[d][c] * W[c][j] ----
    const float4* Ws4 = (const float4*)Ws;
    const float4  bv  = ((const float4*)bs)[lane];

    float4 o[DOMS_PER_WARP];
    #pragma unroll
    for (int g = 0; g < DOMS_PER_WARP; g++) o[g] = bv;

    #pragma unroll 8
    for (int c = 0; c < C_IN; c++) {
        const float4 w = Ws4[c * (C_OUT / 4) + lane];
        #pragma unroll
        for (int g = 0; g < DOMS_PER_WARP; g++) {
            const float s = sums[warp][g][c];  // smem broadcast
            o[g].x = fmaf(s, w.x, o[g].x);
            o[g].y = fmaf(s, w.y, o[g].y);
            o[g].z = fmaf(s, w.z, o[g].z);
            o[g].w = fmaf(s, w.w, o[g].w);
        }
    }

    #pragma unroll
    for (int g = 0; g < DOMS_PER_WARP; g++) {
        const int d = dbase + g;
        if (d < M)
            __stcs(((float4*)(out + (long long)d * C_OUT)) + lane, o[g]);
    }
}

// ---------------------------------------------------------------------------
extern "C" void kernel_launch(void* const* d_in, const int* in_sizes, int n_in,
                              void* d_out, int out_size) {
    const float* features     = (const float*)d_in[0];
    const void*  atom_indices = d_in[1];
    const void*  domain_ids   = d_in[2];
    const float* W            = (const float*)d_in[4];
    const float* b            = (const float*)d_in[5];
    float*       out          = (float*)d_out;

    const int E = in_sizes[1];
    const int M = out_size / C_OUT;

    const int off_threads = 256;
    const int off_blocks  = (M + 1 + off_threads - 1) / off_threads;
    compute_offsets_kernel<<<off_blocks, off_threads>>>(domain_ids, atom_indices, E, M);

    const int blocks = (M + DOMS_PER_BLOCK - 1) / DOMS_PER_BLOCK;
    transfer_fused_kernel<<<blocks, WARPS_PER_BLOCK * 32>>>(
        features, atom_indices, W, b, out, M);
}

// round 5
// speedup vs baseline: 1.2253x; 1.0584x over previous
#include <cuda_runtime.h>
#include <stdint.h>

// ---------------------------------------------------------------------------
// Transfer_35399120453953:
//   gathered    = features[atom_indices]            [E, 64]
//   transferred = segment_sum(gathered, domain_ids) [M, 64]   (domain_ids sorted)
//   out         = transferred @ W + b               [M, 128]
// ---------------------------------------------------------------------------

#define C_IN   64
#define C_OUT  128
#define WARPS_PER_BLOCK 8
#define DOMS_PER_WARP   4
#define DOMS_PER_BLOCK  (WARPS_PER_BLOCK * DOMS_PER_WARP)

__device__ int g_offsets[1048577];

// dtype sniff: int64 LE => high words of first 16 entries are 0.
// atom_indices is random in [0, N_ATOMS) so int32 data fails this w.h.p.
__device__ __forceinline__ int detect_is64(const void* p_) {
    const int* p = (const int*)p_;
    int all_zero = 1;
    #pragma unroll
    for (int k = 0; k < 16; k++) all_zero &= (p[2 * k + 1] == 0);
    return all_zero;
}

__device__ __forceinline__ long long load_index(const void* p, int e, int is64) {
    if (is64) return ((const long long*)p)[e];
    return (long long)((const int*)p)[e];
}

// packed fp32x2 FMA (sm_103a FFMA2) — bitwise identical to 2x fmaf (RN)
__device__ __forceinline__ void fma2(unsigned long long& d,
                                     unsigned long long a,
                                     unsigned long long b) {
    asm("fma.rn.f32x2 %0, %1, %2, %0;" : "+l"(d) : "l"(a), "l"(b));
}
__device__ __forceinline__ unsigned long long pack2(float lo, float hi) {
    unsigned long long r;
    asm("mov.b64 %0, {%1, %2};" : "=l"(r) : "f"(lo), "f"(hi));
    return r;
}

// ---------------------------------------------------------------------------
// Kernel 1: offsets[d] = lower_bound(domain_ids, d) for d in [0, M]
// ---------------------------------------------------------------------------
__global__ void compute_offsets_kernel(const void* __restrict__ domain_ids,
                                       const void* __restrict__ atom_indices,
                                       int E, int M) {
    const int is64 = detect_is64(atom_indices);
    int d = blockIdx.x * blockDim.x + threadIdx.x;
    if (d > M) return;
    int lo = 0, hi = E;
    while (lo < hi) {
        int mid = (lo + hi) >> 1;
        long long v = load_index(domain_ids, mid, is64);
        if (v < (long long)d) lo = mid + 1; else hi = mid;
    }
    g_offsets[d] = lo;
}

// ---------------------------------------------------------------------------
// Kernel 2: fused gather + segment-sum + [64]x[64,128] projection.
// Phase 1 (identical to the best-measured round-2 config): one warp handles
// 4 consecutive domains sequentially; 16 lanes x float4 cover one 256B row,
// lane halves take even/odd entries, merged via shfl_xor(16).
// Phase 2 (new): NO smem staging of sums — acc stays in registers of lanes
// 0..15 and is broadcast per-channel with compile-time shfl (c>>2 lane,
// c&3 component). FMAs are packed fp32x2 (FFMA2) halving FMA issue count.
// ---------------------------------------------------------------------------
__global__ __launch_bounds__(WARPS_PER_BLOCK * 32)
void transfer_fused_kernel(const float* __restrict__ features,
                           const void* __restrict__ atom_indices,
                           const float* __restrict__ W,
                           const float* __restrict__ b,
                           float* __restrict__ out,
                           int M) {
    __shared__ float Ws[C_IN * C_OUT];                           // 32 KB
    __shared__ float bs[C_OUT];

    const int tid  = threadIdx.x;
    const int lane = tid & 31;
    const int warp = tid >> 5;

    #pragma unroll
    for (int i = tid; i < C_IN * C_OUT; i += WARPS_PER_BLOCK * 32)
        Ws[i] = W[i];
    if (tid < C_OUT) bs[tid] = b[tid];
    __syncthreads();

    const int is64  = detect_is64(atom_indices);
    const int dbase = (blockIdx.x * WARPS_PER_BLOCK + warp) * DOMS_PER_WARP;
    if (dbase >= M) return;

    const int half = lane >> 4;   // 0: even entries, 1: odd entries
    const int l16  = lane & 15;   // floats 4*l16 .. 4*l16+3 of the row

    // ---- phase 1: per-domain segment sums (round-2 structure) ----
    float4 acc[DOMS_PER_WARP];
    #pragma unroll
    for (int g = 0; g < DOMS_PER_WARP; g++) {
        const int d = dbase + g;
        float4 a4 = make_float4(0.f, 0.f, 0.f, 0.f);
        if (d < M) {
            const int s0 = g_offsets[d];
            const int s1 = g_offsets[d + 1];
            #pragma unroll 4
            for (int e = s0 + half; e < s1; e += 2) {
                const long long a = load_index(atom_indices, e, is64);
                const float4 v =
                    __ldg(((const float4*)(features + a * C_IN)) + l16);
                a4.x += v.x; a4.y += v.y; a4.z += v.z; a4.w += v.w;
            }
        }
        // combine even/odd halves: lanes 0..15 end with full channel sums
        a4.x += __shfl_xor_sync(0xffffffffu, a4.x, 16);
        a4.y += __shfl_xor_sync(0xffffffffu, a4.y, 16);
        a4.z += __shfl_xor_sync(0xffffffffu, a4.z, 16);
        a4.w += __shfl_xor_sync(0xffffffffu, a4.w, 16);
        acc[g] = a4;
    }

    // ---- phase 2: out[d][j] = b[j] + sum_c acc[d][c] * W[c][j] ----
    // lane j covers output columns 4j..4j+3 as two packed f32x2 pairs.
    const float4* Ws4 = (const float4*)Ws;
    const float4  bv  = ((const float4*)bs)[lane];

    unsigned long long o01[DOMS_PER_WARP], o23[DOMS_PER_WARP];
    #pragma unroll
    for (int g = 0; g < DOMS_PER_WARP; g++) {
        o01[g] = pack2(bv.x, bv.y);
        o23[g] = pack2(bv.z, bv.w);
    }

    #pragma unroll
    for (int c = 0; c < C_IN; c++) {
        const float4 w = Ws4[c * (C_OUT / 4) + lane];
        const unsigned long long w01 = pack2(w.x, w.y);
        const unsigned long long w23 = pack2(w.z, w.w);
        #pragma unroll
        for (int g = 0; g < DOMS_PER_WARP; g++) {
            // broadcast channel c of domain g from lane c>>2, component c&3
            float s;
            switch (c & 3) {
                case 0: s = __shfl_sync(0xffffffffu, acc[g].x, c >> 2); break;
                case 1: s = __shfl_sync(0xffffffffu, acc[g].y, c >> 2); break;
                case 2: s = __shfl_sync(0xffffffffu, acc[g].z, c >> 2); break;
                default:s = __shfl_sync(0xffffffffu, acc[g].w, c >> 2); break;
            }
            const unsigned long long ss = pack2(s, s);
            fma2(o01[g], ss, w01);
            fma2(o23[g], ss, w23);
        }
    }

    #pragma unroll
    for (int g = 0; g < DOMS_PER_WARP; g++) {
        const int d = dbase + g;
        if (d < M) {
            float4 o;
            asm("mov.b64 {%0, %1}, %2;" : "=f"(o.x), "=f"(o.y) : "l"(o01[g]));
            asm("mov.b64 {%0, %1}, %2;" : "=f"(o.z), "=f"(o.w) : "l"(o23[g]));
            ((float4*)(out + (long long)d * C_OUT))[lane] = o;
        }
    }
}

// ---------------------------------------------------------------------------
extern "C" void kernel_launch(void* const* d_in, const int* in_sizes, int n_in,
                              void* d_out, int out_size) {
    const float* features     = (const float*)d_in[0];
    const void*  atom_indices = d_in[1];
    const void*  domain_ids   = d_in[2];
    const float* W            = (const float*)d_in[4];
    const float* b            = (const float*)d_in[5];
    float*       out          = (float*)d_out;

    const int E = in_sizes[1];
    const int M = out_size / C_OUT;

    const int off_threads = 256;
    const int off_blocks  = (M + 1 + off_threads - 1) / off_threads;
    compute_offsets_kernel<<<off_blocks, off_threads>>>(domain_ids, atom_indices, E, M);

    const int blocks = (M + DOMS_PER_BLOCK - 1) / DOMS_PER_BLOCK;
    transfer_fused_kernel<<<blocks, WARPS_PER_BLOCK * 32>>>(
        features, atom_indices, W, b, out, M);
}